// round 6
// baseline (speedup 1.0000x reference)
#include <cuda_runtime.h>
#include <stdint.h>

#define GRID_RES 64
#define BB 8
#define NN 4096
#define KC 18                       // k-chunks per batch -> 144 blocks
#define CH ((NN + KC - 1) / KC)     // 228 points per chunk
#define TILE 32
#define RF_STRIDE 200               // 192 + pad (800B rows, 8B/16B aligned)
#define CF_STRIDE 72                // 68 used + pad (288B rows, 16B aligned)
#define PART_ELEMS (3 * 64 * 64)

__device__ float g_partial[BB * KC * PART_ELEMS];

typedef unsigned long long u64;

__device__ __forceinline__ float ex2f(float x) {
    float r;
    asm("ex2.approx.f32 %0, %1;" : "=f"(r) : "f"(x));
    return r;
}

// packed f32x2 FMA: d = a*b + d, componentwise (sm_103a FFMA2)
#define FMA2(d, a, b) asm("fma.rn.f32x2 %0, %1, %2, %0;" : "+l"(d) : "l"(a), "l"(b))
// replicate one float into both halves of a b64
#define PACK2(d, f)   asm("mov.b64 %0, {%1, %1};" : "=l"(d) : "f"(f))

// CF padded index: +4 floats after every 32 -> the eight 8-col groups hit
// banks {0-3,8-11,16-19,24-27,4-7,12-15,20-23,28-31}: conflict-free LDS.128
__device__ __forceinline__ int cf_pad(int jx) { return jx + ((jx >> 5) << 2); }

__global__ __launch_bounds__(128)
void rbf_partial_kernel(const float* __restrict__ xc,
                        const float* __restrict__ yc,
                        const float* __restrict__ tc,
                        const int* __restrict__ mask) {
    const int b = blockIdx.y;
    const int kc = blockIdx.x;
    const int tid = threadIdx.x;

    const float CEXP = -72.13475204444817f;  // -50 * log2(e)
    const float STEP = 2.0f / 63.0f;

    __shared__ float sRF[TILE][RF_STRIDE];   // [ch*64 + iy]: wy, wy*y, wy*t
    __shared__ float sCF[TILE][CF_STRIDE];   // wx, pad-interleaved
    __shared__ float sP[TILE][8];            // px, py, y, t, maskf

    // stage-B tile: 4 rows x 8 cols x 3 ch = 96 accs = 48 f32x2
    // acc[ch*16 + pr*8 + c] packs (row rbase+2pr, row rbase+2pr+1) at col cg+c
    u64 acc[48];
#pragma unroll
    for (int i = 0; i < 48; i++) acc[i] = 0ULL;

    const int iyq = tid >> 3;            // 0..15
    const int rbase = iyq << 2;          // row quad base
    const int cg = (tid & 7) << 3;       // col group base (8 cols)
    const int cfp = cf_pad(cg);

    // stage-A roles
    const float gy = -1.0f + STEP * (float)tid;          // tid < 64
    const int jx = tid - 64;                              // tid >= 64
    const float gx = -1.0f + STEP * (float)jx;
    const int jxp = (jx >= 0) ? cf_pad(jx) : 0;

    const int p0 = kc * CH;
    const int p1 = min(p0 + CH, NN);

    for (int base = p0; base < p1; base += TILE) {
        const int np = min(TILE, p1 - base);

        if (tid < np) {
            const int n = base + tid;
            sP[tid][0] = xc[(b * NN + n) * 2 + 0];
            sP[tid][1] = xc[(b * NN + n) * 2 + 1];
            sP[tid][2] = yc[b * NN + n];
            sP[tid][3] = tc[b * NN + n];
            sP[tid][4] = (mask[b * NN + n] != 0) ? 0.0f : 1.0f;  // drop -> 0
        }
        __syncthreads();

        if (tid < 64) {
            for (int p = 0; p < np; p++) {
                const float dy = sP[p][1] - gy;
                const float wy = ex2f(CEXP * dy * dy) * sP[p][4];
                sRF[p][tid] = wy;
                sRF[p][64 + tid] = wy * sP[p][2];
                sRF[p][128 + tid] = wy * sP[p][3];
            }
        } else {
            for (int p = 0; p < np; p++) {
                const float dx = sP[p][0] - gx;
                sCF[p][jxp] = ex2f(CEXP * dx * dx);
            }
        }
        __syncthreads();

#pragma unroll 2
        for (int p = 0; p < np; p++) {
            const float4 cA = *(const float4*)&sCF[p][cfp];
            const float4 cB = *(const float4*)&sCF[p][cfp + 4];
            u64 cp[8];
            PACK2(cp[0], cA.x); PACK2(cp[1], cA.y);
            PACK2(cp[2], cA.z); PACK2(cp[3], cA.w);
            PACK2(cp[4], cB.x); PACK2(cp[5], cB.y);
            PACK2(cp[6], cB.z); PACK2(cp[7], cB.w);
#pragma unroll
            for (int ch = 0; ch < 3; ch++) {
                const u64 r0 = *(const u64*)&sRF[p][ch * 64 + rbase];      // rows +0,+1
                const u64 r1 = *(const u64*)&sRF[p][ch * 64 + rbase + 2];  // rows +2,+3
#pragma unroll
                for (int c = 0; c < 8; c++) {
                    FMA2(acc[ch * 16 + c], r0, cp[c]);
                    FMA2(acc[ch * 16 + 8 + c], r1, cp[c]);
                }
            }
        }
        __syncthreads();
    }

    // write partials: layout [ch][iy][jx] = ch*4096 + iy*64 + jx
    float* dst = &g_partial[(b * KC + kc) * PART_ELEMS];
#pragma unroll
    for (int ch = 0; ch < 3; ch++) {
#pragma unroll
        for (int pr = 0; pr < 2; pr++) {
#pragma unroll
            for (int c = 0; c < 8; c++) {
                float lo, hi;
                asm("mov.b64 {%0, %1}, %2;" : "=f"(lo), "=f"(hi)
                    : "l"(acc[ch * 16 + pr * 8 + c]));
                const int r0 = rbase + 2 * pr;
                dst[ch * 4096 + r0 * 64 + cg + c] = lo;
                dst[ch * 4096 + (r0 + 1) * 64 + cg + c] = hi;
            }
        }
    }
}

__global__ __launch_bounds__(64)
void rbf_finalize_kernel(float* __restrict__ out) {
    // one thread per float4 of grid cells; fully unrolled kc loop -> high MLP
    const int idx = blockIdx.x * blockDim.x + threadIdx.x;   // 8192 threads
    const int b = idx >> 10;
    const int g4 = idx & 1023;

    float4 s0 = make_float4(0.f, 0.f, 0.f, 0.f);
    float4 s1 = s0, s2 = s0;
#pragma unroll
    for (int kc = 0; kc < KC; kc++) {
        const float* p = &g_partial[(b * KC + kc) * PART_ELEMS + g4 * 4];
        const float4 a = *(const float4*)&p[0];
        const float4 c = *(const float4*)&p[4096];
        const float4 d = *(const float4*)&p[8192];
        s0.x += a.x; s0.y += a.y; s0.z += a.z; s0.w += a.w;
        s1.x += c.x; s1.y += c.y; s1.z += c.z; s1.w += c.w;
        s2.x += d.x; s2.y += d.y; s2.z += d.z; s2.w += d.w;
    }
    const float4 inv = make_float4(1.f / (s0.x + 1e-5f), 1.f / (s0.y + 1e-5f),
                                   1.f / (s0.z + 1e-5f), 1.f / (s0.w + 1e-5f));
    float* o = out + b * PART_ELEMS + g4 * 4;
    *(float4*)&o[0] = s0;
    *(float4*)&o[4096] = make_float4(s1.x * inv.x, s1.y * inv.y, s1.z * inv.z, s1.w * inv.w);
    *(float4*)&o[8192] = make_float4(s2.x * inv.x, s2.y * inv.y, s2.z * inv.z, s2.w * inv.w);
}

extern "C" void kernel_launch(void* const* d_in, const int* in_sizes, int n_in,
                              void* d_out, int out_size) {
    const float* xc = (const float*)d_in[0];
    const float* yc = (const float*)d_in[1];
    const float* tc = (const float*)d_in[2];
    const int* mask = (const int*)d_in[3];

    dim3 grid(KC, BB);
    rbf_partial_kernel<<<grid, 128>>>(xc, yc, tc, mask);

    rbf_finalize_kernel<<<128, 64>>>((float*)d_out);
}

// round 7
// speedup vs baseline: 1.6843x; 1.6843x over previous
#include <cuda_runtime.h>
#include <stdint.h>

#define GRID_RES 64
#define BB 8
#define NN 4096
#define KC 37                         // 296 blocks = exactly 2 waves-resident (148*2)
#define CH 111                        // ceil(4096/37)
#define TILE 16
#define TTILES 7                      // ceil(111/16), tail padded with mask=drop
#define RF_STRIDE 194                 // 192 + pad
#define CF_STRIDE 72                  // 68 used + pad
#define PART_ELEMS (3 * 64 * 64)

__device__ float g_partial[BB * KC * PART_ELEMS];

typedef unsigned long long u64;

__device__ __forceinline__ float ex2f(float x) {
    float r;
    asm("ex2.approx.f32 %0, %1;" : "=f"(r) : "f"(x));
    return r;
}

// packed f32x2 FMA: d += a*b componentwise (sm_103a)
#define FMA2(d, a, b) asm("fma.rn.f32x2 %0, %1, %2, %0;" : "+l"(d) : "l"(a), "l"(b))
#define PACK2(d, f)   asm("mov.b64 %0, {%1, %1};" : "=l"(d) : "f"(f))
#define UNPACK2(lo, hi, d) asm("mov.b64 {%0, %1}, %2;" : "=f"(lo), "=f"(hi) : "l"(d))

// +4-float gap after every 32 CF columns -> conflict-free LDS.128 groups
__device__ __forceinline__ int cf_pad(int jx) { return jx + ((jx >> 5) << 2); }

__global__ __launch_bounds__(256, 2)
void rbf_partial_kernel(const float* __restrict__ xc,
                        const float* __restrict__ yc,
                        const float* __restrict__ tc,
                        const int* __restrict__ mask) {
    const int b = blockIdx.y;
    const int kc = blockIdx.x;
    const int tid = threadIdx.x;

    const float CEXP = -72.13475204444817f;  // -50 * log2(e)
    const float STEP = 2.0f / 63.0f;

    __shared__ float sRF[2][TILE][RF_STRIDE]; // [ch*64+iy]: wy, wy*y, wy*t
    __shared__ float sCF[2][TILE][CF_STRIDE]; // wx, pad-interleaved
    __shared__ float sP[2][TILE][8];          // px, py, y, t, maskf

    // stage-B: thread owns row-pair (2*rp, 2*rp+1) x 8 cols x 3 ch
    // acc[ch][c] packs (row iy0, row iy0+1) at col 8*c8+c
    u64 acc[3][8];
#pragma unroll
    for (int ch = 0; ch < 3; ch++)
#pragma unroll
        for (int c = 0; c < 8; c++) acc[ch][c] = 0ULL;

    const int rp = tid >> 3;            // 0..31
    const int iy0 = rp << 1;
    const int c8 = tid & 7;
    const int cfp = cf_pad(c8 << 3);

    // stage-A roles: role 0/2 = RF (y-exps), 1/3 = CF (x-exps); halves of tile
    const int role = tid >> 6;
    const int v = tid & 63;
    const int phalf = (role >> 1) << 3;        // 0 or 8
    const bool isRF = ((role & 1) == 0);
    const float gv = -1.0f + STEP * (float)v;  // gy for RF, gx for CF
    const int vp = cf_pad(v);

    const int p0 = kc * CH;
    const int p1 = min(p0 + CH, NN);

    // point staging registers (tile index tt, thread stages point tid<16)
    float Px = 0.f, Py = 0.f, Yv = 0.f, Tv = 0.f, Mf = 0.f;

#define LOADP(tt)                                                         \
    do {                                                                  \
        if (tid < TILE && (tt) < TTILES) {                                \
            const int n = p0 + (tt) * TILE + tid;                         \
            if (n < p1) {                                                 \
                Px = xc[(b * NN + n) * 2 + 0];                            \
                Py = xc[(b * NN + n) * 2 + 1];                            \
                Yv = yc[b * NN + n];                                      \
                Tv = tc[b * NN + n];                                      \
                Mf = (mask[b * NN + n] != 0) ? 0.0f : 1.0f;               \
            } else { Px = Py = Yv = Tv = Mf = 0.0f; }                     \
        }                                                                 \
    } while (0)

#define STSP(tt)                                                          \
    do {                                                                  \
        if (tid < TILE && (tt) < TTILES) {                                \
            const int bb_ = (tt) & 1;                                     \
            sP[bb_][tid][0] = Px; sP[bb_][tid][1] = Py;                   \
            sP[bb_][tid][2] = Yv; sP[bb_][tid][3] = Tv;                   \
            sP[bb_][tid][4] = Mf;                                         \
        }                                                                 \
    } while (0)

#define STAGE_A(tt)                                                       \
    do {                                                                  \
        const int bb_ = (tt) & 1;                                         \
        if (isRF) {                                                       \
            _Pragma("unroll")                                             \
            for (int q = 0; q < 8; q++) {                                 \
                const int p = phalf + q;                                  \
                const float dy = sP[bb_][p][1] - gv;                      \
                const float wy = ex2f(CEXP * dy * dy) * sP[bb_][p][4];    \
                sRF[bb_][p][v] = wy;                                      \
                sRF[bb_][p][64 + v] = wy * sP[bb_][p][2];                 \
                sRF[bb_][p][128 + v] = wy * sP[bb_][p][3];                \
            }                                                             \
        } else {                                                          \
            _Pragma("unroll")                                             \
            for (int q = 0; q < 8; q++) {                                 \
                const int p = phalf + q;                                  \
                const float dx = sP[bb_][p][0] - gv;                      \
                sCF[bb_][p][vp] = ex2f(CEXP * dx * dx);                   \
            }                                                             \
        }                                                                 \
    } while (0)

#define STAGE_B(tt)                                                       \
    do {                                                                  \
        const int bb_ = (tt) & 1;                                         \
        _Pragma("unroll 4")                                               \
        for (int p = 0; p < TILE; p++) {                                  \
            const float4 cA = *(const float4*)&sCF[bb_][p][cfp];          \
            const float4 cB = *(const float4*)&sCF[bb_][p][cfp + 4];      \
            u64 cp[8];                                                    \
            PACK2(cp[0], cA.x); PACK2(cp[1], cA.y);                       \
            PACK2(cp[2], cA.z); PACK2(cp[3], cA.w);                       \
            PACK2(cp[4], cB.x); PACK2(cp[5], cB.y);                       \
            PACK2(cp[6], cB.z); PACK2(cp[7], cB.w);                       \
            _Pragma("unroll")                                             \
            for (int ch = 0; ch < 3; ch++) {                              \
                const u64 r = *(const u64*)&sRF[bb_][p][ch * 64 + iy0];   \
                _Pragma("unroll")                                         \
                for (int c = 0; c < 8; c++) FMA2(acc[ch][c], r, cp[c]);   \
            }                                                             \
        }                                                                 \
    } while (0)

    // prologue
    LOADP(0); STSP(0);
    LOADP(1); STSP(1);
    LOADP(2);
    __syncthreads();
    STAGE_A(0);
    __syncthreads();

    // pipelined main loop: one barrier per tile
#pragma unroll 1
    for (int t = 0; t < TTILES; t++) {
        STSP(t + 2);            // regs loaded in iter t-1 (or prologue)
        LOADP(t + 3);
        if (t + 1 < TTILES) STAGE_A(t + 1);
        STAGE_B(t);
        __syncthreads();
    }

    // epilogue: [ch][iy][jx] = ch*4096 + iy*64 + jx
    float* dst = &g_partial[(b * KC + kc) * PART_ELEMS];
#pragma unroll
    for (int ch = 0; ch < 3; ch++) {
        float lo[8], hi[8];
#pragma unroll
        for (int c = 0; c < 8; c++) UNPACK2(lo[c], hi[c], acc[ch][c]);
        float* d0 = &dst[ch * 4096 + iy0 * 64 + (c8 << 3)];
        float* d1 = d0 + 64;
        *(float4*)&d0[0] = make_float4(lo[0], lo[1], lo[2], lo[3]);
        *(float4*)&d0[4] = make_float4(lo[4], lo[5], lo[6], lo[7]);
        *(float4*)&d1[0] = make_float4(hi[0], hi[1], hi[2], hi[3]);
        *(float4*)&d1[4] = make_float4(hi[4], hi[5], hi[6], hi[7]);
    }
}

// K2: density reduce (channel 0). 32768 threads, loads hit L2 (14.6MB resident).
__global__ __launch_bounds__(256)
void rbf_density_kernel(float* __restrict__ out) {
    const int idx = blockIdx.x * blockDim.x + threadIdx.x;
    const int b = idx >> 12;
    const int g = idx & 4095;
    const float* base = &g_partial[b * KC * PART_ELEMS + g];
    float s = 0.0f;
#pragma unroll
    for (int kcc = 0; kcc < KC; kcc++) s += base[kcc * PART_ELEMS];
    out[b * PART_ELEMS + g] = s;
}

// K3: weighted channels + divide by (density + eps). 65536 threads.
__global__ __launch_bounds__(256)
void rbf_weighted_kernel(float* __restrict__ out) {
    const int idx = blockIdx.x * blockDim.x + threadIdx.x;
    const int b = idx >> 13;
    const int r = idx & 8191;
    const int ch = 1 + (r >> 12);
    const int g = r & 4095;
    const float* base = &g_partial[b * KC * PART_ELEMS + ch * 4096 + g];
    float s = 0.0f;
#pragma unroll
    for (int kcc = 0; kcc < KC; kcc++) s += base[kcc * PART_ELEMS];
    const float d = out[b * PART_ELEMS + g];
    out[b * PART_ELEMS + ch * 4096 + g] = s / (d + 1e-5f);
}

extern "C" void kernel_launch(void* const* d_in, const int* in_sizes, int n_in,
                              void* d_out, int out_size) {
    const float* xc = (const float*)d_in[0];
    const float* yc = (const float*)d_in[1];
    const float* tc = (const float*)d_in[2];
    const int* mask = (const int*)d_in[3];

    dim3 grid(KC, BB);
    rbf_partial_kernel<<<grid, 256>>>(xc, yc, tc, mask);

    rbf_density_kernel<<<128, 256>>>((float*)d_out);
    rbf_weighted_kernel<<<256, 256>>>((float*)d_out);
}